// round 13
// baseline (speedup 1.0000x reference)
#include <cuda_runtime.h>
#include <stdint.h>

// MaskPyramids single-pass, single-launch, 128B-line-aligned STG.128 stores
// (R12) + WARP-UNIFORM zero fast path (new): a warp's 32 f4s span <=2 grid
// rows; if neither row intersects the 28-row window band (true ~86% of the
// time), every lane stores a zero float4 with no per-lane window math.
//
// grid = (14, 512): bx 0-9 -> level 200x200, bx 10-12 -> level 100x100,
// bx 13 -> levels 50/25/13 (scalar tail levels). Head/tail of each aligned
// region handled by spare threads of chunk 0 (as in R12, verified).
//
// Rounding replicates XLA's div->reciprocal-mul rewrite (verified exact R3):
//   rint( fl( fl(p * fl(1/200)) * H ) ), all f32 RN-even.

#define N_INST   512
#define G        28
#define CTRK     13
#define PER_INST 53294   // 40000 + 10000 + 2500 + 625 + 169

__device__ __forceinline__ float mval(const float* __restrict__ mask,
                                      int si, int sj) {
    return ((unsigned)si < (unsigned)G && (unsigned)sj < (unsigned)G)
               ? __ldg(&mask[si * G + sj]) : 0.0f;
}

template<int H>
__device__ __forceinline__ void do_level(int chunk, int c0, int b0, int h,
                                         const float* __restrict__ mask,
                                         float* __restrict__ outlevel) {
    constexpr int NELEM = H * H;
    const int NB  = (NELEM - h) >> 2;        // aligned-body f4 count
    const int tid = threadIdx.x;
    const int wbase0 = chunk * 1024 + (tid & ~31);   // warp's first f4, k=0

    #pragma unroll
    for (int k = 0; k < 4; k++) {
        const int f4 = chunk * 1024 + k * 256 + tid;
        if (f4 >= NB) break;

        // warp-uniform window-row intersection test (lane-redundant, uniform)
        const int S  = h + (wbase0 + k * 256) * 4;   // warp's first float off
        const int rA = S / H;                        // compile-time magic div
        const int rB = (S + 127) / H;
        const bool warp_hit = (rB + c0 >= 0) && (rA + c0 <= G - 1);

        const int off = h + f4 * 4;
        if (!warp_hit) {
            *reinterpret_cast<float4*>(outlevel + off) =
                make_float4(0.f, 0.f, 0.f, 0.f);
        } else {
            const int row = off / H;
            const int col = off - row * H;
            const int si  = row + c0;
            float4 v = make_float4(0.f, 0.f, 0.f, 0.f);
            if (col <= H - 4) {                      // no row straddle
                const int sj = col - b0;
                if ((unsigned)si < (unsigned)G && sj > -4 && sj < G) {
                    const float* mrow = mask + si * G;
                    if ((unsigned)(sj + 0) < (unsigned)G) v.x = __ldg(&mrow[sj + 0]);
                    if ((unsigned)(sj + 1) < (unsigned)G) v.y = __ldg(&mrow[sj + 1]);
                    if ((unsigned)(sj + 2) < (unsigned)G) v.z = __ldg(&mrow[sj + 2]);
                    if ((unsigned)(sj + 3) < (unsigned)G) v.w = __ldg(&mrow[sj + 3]);
                }
            } else {                                 // straddle (h%4!=0, rare)
                float ve[4];
                #pragma unroll
                for (int e = 0; e < 4; e++) {
                    int c = col + e, r = si;
                    if (c >= H) { c -= H; r += 1; }
                    ve[e] = mval(mask, r, c - b0);
                }
                v = make_float4(ve[0], ve[1], ve[2], ve[3]);
            }
            *reinterpret_cast<float4*>(outlevel + off) = v;
        }
    }

    if (chunk == 0) {
        // head: elements [0, h), all in row 0
        if (tid < h)
            outlevel[tid] = mval(mask, c0, tid - b0);
        // tail: t = (NELEM - h) & 3 elements at the very end, row H-1
        const int t = (NELEM - h) & 3;
        const int j = tid - 64;
        if (j >= 0 && j < t)
            outlevel[NELEM - t + j] = mval(mask, H - 1 + c0, H - t + j - b0);
    }
}

template<int H, int BASE, int N>
__device__ __forceinline__ void do_tail_level(float pp0, float pp1,
                                              const float* __restrict__ mask,
                                              float* __restrict__ outrow) {
    const int lh = (int)rintf(__fmul_rn(pp0, (float)H));
    const int lw = (int)rintf(__fmul_rn(pp1, (float)H));
    const int c0 = CTRK - lh;
    const int b0 = lw - CTRK;
    for (int idx = threadIdx.x; idx < N; idx += 256) {
        const int row = idx / H;                // compile-time magic div
        const int col = idx - row * H;
        outrow[BASE + idx] = mval(mask, row + c0, col - b0);
    }
}

__global__ void __launch_bounds__(256)
fused_kernel(const int* __restrict__ pos,
             const float* __restrict__ mask,
             float* __restrict__ out) {
    const int inst = blockIdx.y;
    const int bx   = blockIdx.x;

    const float recip = 0.005f;  // fl(1/200) bit-exactly
    const float pp0 = __fmul_rn((float)__ldg(&pos[2 * inst + 0]), recip);
    const float pp1 = __fmul_rn((float)__ldg(&pos[2 * inst + 1]), recip);

    float* outrow = out + inst * PER_INST;
    // head length to first 128B line; level bases (0, 40000) are 0 mod 32 so
    // the same h applies to both big levels.
    const int h = (32 - ((inst * PER_INST) & 31)) & 31;

    if (bx < 10) {
        const int c0 = CTRK - (int)rintf(__fmul_rn(pp0, 200.f));
        const int b0 = (int)rintf(__fmul_rn(pp1, 200.f)) - CTRK;
        do_level<200>(bx, c0, b0, h, mask, outrow);
    } else if (bx < 13) {
        const int c0 = CTRK - (int)rintf(__fmul_rn(pp0, 100.f));
        const int b0 = (int)rintf(__fmul_rn(pp1, 100.f)) - CTRK;
        do_level<100>(bx - 10, c0, b0, h, mask, outrow + 40000);
    } else {
        do_tail_level<50, 50000, 2500>(pp0, pp1, mask, outrow);
        do_tail_level<25, 52500, 625>(pp0, pp1, mask, outrow);
        do_tail_level<13, 53125, 169>(pp0, pp1, mask, outrow);
    }
}

extern "C" void kernel_launch(void* const* d_in, const int* in_sizes, int n_in,
                              void* d_out, int out_size) {
    const int*   pos  = (const int*)d_in[0];      // int32 [512, 2]
    const float* mask = (const float*)d_in[1];    // float32 [28, 28]
    float*       out  = (float*)d_out;            // float32 [512, 53294]

    fused_kernel<<<dim3(14, N_INST), 256>>>(pos, mask, out);
}